// round 11
// baseline (speedup 1.0000x reference)
#include <cuda_runtime.h>
#include <math.h>

// Problem constants
#define Bc 64
#define Tc 128
#define Dc 1024
#define MU 8192            // B*T rows of xs

#define ROWS_PER_BLK 8
#define NBLK (MU / ROWS_PER_BLK)   // 1024

// Scratch (device globals: allocation-free per harness rules)
__device__ float g_xs[MU];
__device__ unsigned int g_done;   // zero at load; reset by last block each run

// ---------------------------------------------------------------------------
// Single launch.
// Phase 1 (all 1024 blocks x 256 thr): xs[b,t] = x[b,t].w_x — exact R4
//   geometry: 8 rows/block, 1 weight float4 + 8 independent LDG.128/thread.
// Epilogue: ONLY tid 0 fences + bumps the done-counter (R7's regression came
//   from all 256 threads issuing gpu-scope MEMBARs).
// Phase 2 (elected last block): full loss, 8 warps x 8 batches:
//   loss_row(j) = log( sum_{t=j+2}^{len-1} exp(xs_t - M) ) + M - xs_{j+2}
//   (LSTM head + fc_b cancel along the softmax axis -> dead inputs.)
//   Suffix sums via warp shfl_down suffix scan; fixed-order final fold.
// ---------------------------------------------------------------------------
__global__ __launch_bounds__(256) void fused_kernel(const float* __restrict__ x,
                                                    const float* __restrict__ fc_w,
                                                    const int* __restrict__ mask,
                                                    float* __restrict__ out) {
    const int tid  = threadIdx.x;
    const int lane = tid & 31;
    const int warp = tid >> 5;

    // ---- Phase 1: xs for 8 rows (R4-proven streaming shape) ----
    {
        const int r0 = blockIdx.x * ROWS_PER_BLK;
        const float4* xb = (const float4*)(x + (size_t)r0 * Dc);
        const float4  w  = ((const float4*)(fc_w + 512))[tid];

        float4 a[ROWS_PER_BLK];
#pragma unroll
        for (int i = 0; i < ROWS_PER_BLK; i++)
            a[i] = xb[i * 256 + tid];          // 8 independent LDG.128 in flight

        float s[ROWS_PER_BLK];
#pragma unroll
        for (int i = 0; i < ROWS_PER_BLK; i++)
            s[i] = a[i].x * w.x + a[i].y * w.y + a[i].z * w.z + a[i].w * w.w;

#pragma unroll
        for (int off = 16; off; off >>= 1)
#pragma unroll
            for (int i = 0; i < ROWS_PER_BLK; i++)
                s[i] += __shfl_xor_sync(0xffffffffu, s[i], off);

        __shared__ float wsum[8][ROWS_PER_BLK];
        if (lane == 0) {
#pragma unroll
            for (int i = 0; i < ROWS_PER_BLK; i++) wsum[warp][i] = s[i];
        }
        __syncthreads();
        if (tid < ROWS_PER_BLK) {
            float t = 0.f;
#pragma unroll
            for (int k = 0; k < 8; k++) t += wsum[k][tid];
            g_xs[r0 + tid] = t;
        }
    }

    // ---- election: single gpu-fence + atomic per BLOCK (tid 0 only) ----
    __shared__ unsigned int s_last;
    __syncthreads();                    // orders the g_xs stores with tid 0
    if (tid == 0) {
        __threadfence();                // publish this block's g_xs slice
        s_last = atomicAdd(&g_done, 1u);
    }
    __syncthreads();
    if (s_last != NBLK - 1) return;
    __threadfence();                    // acquire all blocks' g_xs

    // ---- Phase 2: loss, 8 warps x 8 batches each ----
    __shared__ float s_tot[8];
    __shared__ float s_cnt[8];

    float acc = 0.f;
    float cntf = 0.f;

#pragma unroll
    for (int k = 0; k < 8; k++) {
        const int b = warp + k * 8;

        // len = sum(mask[b,:]) : int4 per lane
        const int4 mv = ((const int4*)(mask + b * Tc))[lane];
        int len = mv.x + mv.y + mv.z + mv.w;
#pragma unroll
        for (int off = 16; off; off >>= 1)
            len += __shfl_xor_sync(0xffffffffu, len, off);

        // xs row: 4 chunks of 32 (L2-resident)
        float v[4];
#pragma unroll
        for (int c = 0; c < 4; c++)
            v[c] = g_xs[b * Tc + c * 32 + lane];

        // per-batch max (constant shift; xs is O(1) so no overflow risk)
        float M = fmaxf(fmaxf(v[0], v[1]), fmaxf(v[2], v[3]));
#pragma unroll
        for (int off = 16; off; off >>= 1)
            M = fmaxf(M, __shfl_xor_sync(0xffffffffu, M, off));

        // masked exponentials
        float e[4];
#pragma unroll
        for (int c = 0; c < 4; c++) {
            const int t = c * 32 + lane;
            e[c] = (t < len) ? __expf(v[c] - M) : 0.f;
        }

        // suffix-sum scan, chunk 3 -> 0, carry = sum of later chunks
        float carry = 0.f;
#pragma unroll
        for (int c = 3; c >= 0; c--) {
            float ss = e[c];
#pragma unroll
            for (int off = 1; off < 32; off <<= 1) {
                float s2 = __shfl_down_sync(0xffffffffu, ss, off);
                ss += ((lane + off) < 32) ? s2 : 0.f;
            }
            ss += carry;
            const int t = c * 32 + lane;
            if (t >= 2 && t < len)
                acc += __logf(ss) + M - v[c];
            carry = __shfl_sync(0xffffffffu, ss, 0);
        }

        if (lane == 0) {
            int cnt = len - 2;
            if (cnt < 0) cnt = 0;
            cntf += (float)cnt;
        }
    }

    // warp-reduce acc (fixed order -> deterministic)
#pragma unroll
    for (int off = 16; off; off >>= 1)
        acc += __shfl_xor_sync(0xffffffffu, acc, off);

    if (lane == 0) { s_tot[warp] = acc; s_cnt[warp] = cntf; }
    __syncthreads();

    if (tid == 0) {
        float tot = 0.f, cnt = 0.f;
#pragma unroll
        for (int k = 0; k < 8; k++) { tot += s_tot[k]; cnt += s_cnt[k]; }
        out[0] = (cnt > 0.f) ? tot / cnt : 0.f;
        g_done = 0;                      // reset for next graph replay
    }
}

// ---------------------------------------------------------------------------
extern "C" void kernel_launch(void* const* d_in, const int* in_sizes, int n_in,
                              void* d_out, int out_size) {
    const float* x    = (const float*)d_in[0];
    const int*   mask = (const int*)d_in[1];
    // d_in[2..5] (W_ih, W_hh, b_ih, b_hh) and fc_b are dead: the LSTM head
    // contribution is constant along the logsumexp axis and cancels exactly.
    const float* fc_w = (const float*)d_in[6];
    float* out = (float*)d_out;

    fused_kernel<<<NBLK, 256>>>(x, fc_w, mask, out);
}

// round 12
// speedup vs baseline: 1.3616x; 1.3616x over previous
#include <cuda_runtime.h>
#include <math.h>

// Problem constants
#define Bc 64
#define Tc 128
#define Dc 1024
#define MU 8192            // B*T rows of xs

#define ROWS_PER_BLK 8
#define NBLK (MU / ROWS_PER_BLK)   // 1024

// Scratch (device globals: allocation-free per harness rules)
__device__ float g_xs[MU];
__device__ float g_partial[2 * Bc];
__device__ unsigned int g_done;    // xs-complete counter (reset each run)
__device__ unsigned int g_done2;   // loss-complete counter (reset each run)

// ---------------------------------------------------------------------------
// Single launch, spread loss.
// Phase 1 (all 1024 blocks x 256 thr): xs[b,t] = x[b,t].w_x — R4-proven
//   shape: 8 rows/block, 1 weight float4 + 8 independent LDG.128/thread.
// Phase 2 (blocks 0..63, warp 0): poll until all xs done, then compute the
//   loss for batch b = blockIdx.x IN PARALLEL across 64 SMs:
//   loss_row(j) = log( sum_{t=j+2}^{len-1} exp(xs_t - M) ) + M - xs_{j+2}
//   (LSTM head + fc_b cancel along the softmax axis -> dead inputs.)
// Phase 3 (last of the 64): fixed-order fold of 64 partials -> out.
// ---------------------------------------------------------------------------
__global__ __launch_bounds__(256) void fused_kernel(const float* __restrict__ x,
                                                    const float* __restrict__ fc_w,
                                                    const int* __restrict__ mask,
                                                    float* __restrict__ out) {
    const int tid  = threadIdx.x;
    const int lane = tid & 31;
    const int warp = tid >> 5;
    const int bid  = blockIdx.x;

    // Prefetch mask for designated blocks (latency hidden behind xs phase)
    int4 mv = make_int4(0, 0, 0, 0);
    if (bid < Bc && warp == 0)
        mv = ((const int4*)(mask + bid * Tc))[lane];

    // ---- Phase 1: xs for 8 rows ----
    {
        const int r0 = bid * ROWS_PER_BLK;
        const float4* xb = (const float4*)(x + (size_t)r0 * Dc);
        const float4  w  = ((const float4*)(fc_w + 512))[tid];

        float4 a[ROWS_PER_BLK];
#pragma unroll
        for (int i = 0; i < ROWS_PER_BLK; i++)
            a[i] = xb[i * 256 + tid];          // 8 independent LDG.128 in flight

        float s[ROWS_PER_BLK];
#pragma unroll
        for (int i = 0; i < ROWS_PER_BLK; i++)
            s[i] = a[i].x * w.x + a[i].y * w.y + a[i].z * w.z + a[i].w * w.w;

#pragma unroll
        for (int off = 16; off; off >>= 1)
#pragma unroll
            for (int i = 0; i < ROWS_PER_BLK; i++)
                s[i] += __shfl_xor_sync(0xffffffffu, s[i], off);

        __shared__ float wsum[8][ROWS_PER_BLK];
        if (lane == 0) {
#pragma unroll
            for (int i = 0; i < ROWS_PER_BLK; i++) wsum[warp][i] = s[i];
        }
        __syncthreads();
        if (tid < ROWS_PER_BLK) {
            float t = 0.f;
#pragma unroll
            for (int k = 0; k < 8; k++) t += wsum[k][tid];
            g_xs[r0 + tid] = t;
        }
    }

    __syncthreads();
    if (tid == 0) {
        __threadfence();                 // publish this block's g_xs slice
        atomicAdd(&g_done, 1u);
    }

    if (bid >= Bc || warp != 0) return;  // only warp 0 of blocks 0..63 continue

    // ---- Phase 2: wait for all xs, then this batch's loss ----
    {
        volatile unsigned int* done = &g_done;
        while (*done < NBLK) __nanosleep(64);
    }
    __threadfence();                     // acquire all blocks' g_xs
    __syncwarp();

    const int b = bid;

    int len = mv.x + mv.y + mv.z + mv.w;
#pragma unroll
    for (int off = 16; off; off >>= 1)
        len += __shfl_xor_sync(0xffffffffu, len, off);

    float v[4];
#pragma unroll
    for (int c = 0; c < 4; c++)
        v[c] = g_xs[b * Tc + c * 32 + lane];

    // per-batch max (constant shift; xs is O(1) so no overflow risk)
    float M = fmaxf(fmaxf(v[0], v[1]), fmaxf(v[2], v[3]));
#pragma unroll
    for (int off = 16; off; off >>= 1)
        M = fmaxf(M, __shfl_xor_sync(0xffffffffu, M, off));

    float e[4];
#pragma unroll
    for (int c = 0; c < 4; c++) {
        const int t = c * 32 + lane;
        e[c] = (t < len) ? __expf(v[c] - M) : 0.f;
    }

    // suffix-sum scan, chunk 3 -> 0, carry = sum of later chunks
    float acc = 0.f;
    float carry = 0.f;
#pragma unroll
    for (int c = 3; c >= 0; c--) {
        float ss = e[c];
#pragma unroll
        for (int off = 1; off < 32; off <<= 1) {
            float s2 = __shfl_down_sync(0xffffffffu, ss, off);
            ss += ((lane + off) < 32) ? s2 : 0.f;
        }
        ss += carry;
        const int t = c * 32 + lane;
        if (t >= 2 && t < len)
            acc += __logf(ss) + M - v[c];
        carry = __shfl_sync(0xffffffffu, ss, 0);
    }

    // warp-reduce acc (fixed order -> deterministic)
#pragma unroll
    for (int off = 16; off; off >>= 1)
        acc += __shfl_xor_sync(0xffffffffu, acc, off);

    unsigned int done2 = 0;
    if (lane == 0) {
        int cnt = len - 2;
        if (cnt < 0) cnt = 0;
        g_partial[2 * b]     = acc;
        g_partial[2 * b + 1] = (float)cnt;
        __threadfence();
        done2 = atomicAdd(&g_done2, 1u);
    }
    done2 = __shfl_sync(0xffffffffu, done2, 0);
    if (done2 != Bc - 1) return;

    // ---- Phase 3: last loss-block folds the 64 partials (whole warp) ----
    __threadfence();
    float tot = g_partial[2 * lane]     + g_partial[2 * (lane + 32)];
    float cnt = g_partial[2 * lane + 1] + g_partial[2 * (lane + 32) + 1];
#pragma unroll
    for (int off = 16; off; off >>= 1) {
        tot += __shfl_xor_sync(0xffffffffu, tot, off);
        cnt += __shfl_xor_sync(0xffffffffu, cnt, off);
    }
    if (lane == 0) {
        out[0] = (cnt > 0.f) ? tot / cnt : 0.f;
        g_done  = 0;                     // reset for next graph replay
        g_done2 = 0;
    }
}

// ---------------------------------------------------------------------------
extern "C" void kernel_launch(void* const* d_in, const int* in_sizes, int n_in,
                              void* d_out, int out_size) {
    const float* x    = (const float*)d_in[0];
    const int*   mask = (const int*)d_in[1];
    // d_in[2..5] (W_ih, W_hh, b_ih, b_hh) and fc_b are dead: the LSTM head
    // contribution is constant along the logsumexp axis and cancels exactly.
    const float* fc_w = (const float*)d_in[6];
    float* out = (float*)d_out;

    fused_kernel<<<NBLK, 256>>>(x, fc_w, mask, out);
}

// round 13
// speedup vs baseline: 1.3684x; 1.0050x over previous
#include <cuda_runtime.h>
#include <math.h>

// Problem constants
#define Bc 64
#define Tc 128
#define Dc 1024
#define MU 8192            // B*T rows of xs

#define ROWS_PER_BLK 8
#define NBLK (MU / ROWS_PER_BLK)   // 1024
#define BLKS_PER_BATCH 16          // 16 blocks x 8 rows = 128 rows = one batch

// Scratch (device globals: allocation-free per harness rules)
__device__ float g_xs[MU];
__device__ float g_partial[2 * Bc];
__device__ unsigned int g_cnt[Bc];   // per-batch producer counters (reset each run)
__device__ unsigned int g_done2;     // loss-complete counter (reset each run)

// ---------------------------------------------------------------------------
// Single launch, per-batch pipelining.
// Phase 1 (all 1024 blocks x 256 thr): xs[b,t] = x[b,t].w_x — R4 shape:
//   8 rows/block, 1 weight float4 + 8 independent LDG.128/thread.
//   Each block bumps its BATCH's counter (batch = bid/16).
// Phase 2 (block 16b, warp 0): spin ONLY on g_cnt[b]==16, then compute
//   batch b's loss — overlapped with other batches' streaming:
//   loss_row(j) = log( sum_{t=j+2}^{len-1} exp(xs_t - M) ) + M - xs_{j+2}
//   (LSTM head + fc_b cancel along the softmax axis -> dead inputs.)
// Phase 3 (last of the 64): fixed-order fold of 64 partials -> out, reset.
// ---------------------------------------------------------------------------
__global__ __launch_bounds__(256) void fused_kernel(const float* __restrict__ x,
                                                    const float* __restrict__ fc_w,
                                                    const int* __restrict__ mask,
                                                    float* __restrict__ out) {
    const int tid  = threadIdx.x;
    const int lane = tid & 31;
    const int warp = tid >> 5;
    const int bid  = blockIdx.x;
    const int batch = bid >> 4;                 // 16 blocks per batch
    const bool designated = ((bid & 15) == 0);

    // Prefetch mask for designated blocks (latency hidden behind xs phase)
    int4 mv = make_int4(0, 0, 0, 0);
    if (designated && warp == 0)
        mv = ((const int4*)(mask + batch * Tc))[lane];

    // ---- Phase 1: xs for 8 rows ----
    {
        const int r0 = bid * ROWS_PER_BLK;
        const float4* xb = (const float4*)(x + (size_t)r0 * Dc);
        const float4  w  = ((const float4*)(fc_w + 512))[tid];

        float4 a[ROWS_PER_BLK];
#pragma unroll
        for (int i = 0; i < ROWS_PER_BLK; i++)
            a[i] = xb[i * 256 + tid];          // 8 independent LDG.128 in flight

        float s[ROWS_PER_BLK];
#pragma unroll
        for (int i = 0; i < ROWS_PER_BLK; i++)
            s[i] = a[i].x * w.x + a[i].y * w.y + a[i].z * w.z + a[i].w * w.w;

#pragma unroll
        for (int off = 16; off; off >>= 1)
#pragma unroll
            for (int i = 0; i < ROWS_PER_BLK; i++)
                s[i] += __shfl_xor_sync(0xffffffffu, s[i], off);

        __shared__ float wsum[8][ROWS_PER_BLK];
        if (lane == 0) {
#pragma unroll
            for (int i = 0; i < ROWS_PER_BLK; i++) wsum[warp][i] = s[i];
        }
        __syncthreads();
        if (tid < ROWS_PER_BLK) {
            float t = 0.f;
#pragma unroll
            for (int k = 0; k < 8; k++) t += wsum[k][tid];
            g_xs[r0 + tid] = t;
        }
    }

    __syncthreads();
    if (tid == 0) {
        __threadfence();                 // publish this block's g_xs slice
        atomicAdd(&g_cnt[batch], 1u);
    }

    if (!designated || warp != 0) return;   // only warp 0 of blocks 16b continue

    // ---- Phase 2: wait for THIS batch's 16 producers, then its loss ----
    {
        volatile unsigned int* cnt = &g_cnt[batch];
        while (*cnt < BLKS_PER_BATCH) __nanosleep(32);
    }
    __threadfence();                     // acquire this batch's g_xs rows
    __syncwarp();

    const int b = batch;

    int len = mv.x + mv.y + mv.z + mv.w;
#pragma unroll
    for (int off = 16; off; off >>= 1)
        len += __shfl_xor_sync(0xffffffffu, len, off);

    float v[4];
#pragma unroll
    for (int c = 0; c < 4; c++)
        v[c] = g_xs[b * Tc + c * 32 + lane];

    // per-batch max (constant shift; xs is O(1) so no overflow risk)
    float M = fmaxf(fmaxf(v[0], v[1]), fmaxf(v[2], v[3]));
#pragma unroll
    for (int off = 16; off; off >>= 1)
        M = fmaxf(M, __shfl_xor_sync(0xffffffffu, M, off));

    float e[4];
#pragma unroll
    for (int c = 0; c < 4; c++) {
        const int t = c * 32 + lane;
        e[c] = (t < len) ? __expf(v[c] - M) : 0.f;
    }

    // suffix-sum scan, chunk 3 -> 0, carry = sum of later chunks
    float acc = 0.f;
    float carry = 0.f;
#pragma unroll
    for (int c = 3; c >= 0; c--) {
        float ss = e[c];
#pragma unroll
        for (int off = 1; off < 32; off <<= 1) {
            float s2 = __shfl_down_sync(0xffffffffu, ss, off);
            ss += ((lane + off) < 32) ? s2 : 0.f;
        }
        ss += carry;
        const int t = c * 32 + lane;
        if (t >= 2 && t < len)
            acc += __logf(ss) + M - v[c];
        carry = __shfl_sync(0xffffffffu, ss, 0);
    }

    // warp-reduce acc (fixed order -> deterministic)
#pragma unroll
    for (int off = 16; off; off >>= 1)
        acc += __shfl_xor_sync(0xffffffffu, acc, off);

    unsigned int done2 = 0;
    if (lane == 0) {
        int cnt = len - 2;
        if (cnt < 0) cnt = 0;
        g_partial[2 * b]     = acc;
        g_partial[2 * b + 1] = (float)cnt;
        __threadfence();
        done2 = atomicAdd(&g_done2, 1u);
    }
    done2 = __shfl_sync(0xffffffffu, done2, 0);
    if (done2 != Bc - 1) return;

    // ---- Phase 3: last loss-warp folds the 64 partials (whole warp) ----
    __threadfence();
    float tot = g_partial[2 * lane]     + g_partial[2 * (lane + 32)];
    float cnt = g_partial[2 * lane + 1] + g_partial[2 * (lane + 32) + 1];
#pragma unroll
    for (int off = 16; off; off >>= 1) {
        tot += __shfl_xor_sync(0xffffffffu, tot, off);
        cnt += __shfl_xor_sync(0xffffffffu, cnt, off);
    }
    // reset counters for next graph replay (this warp runs strictly last)
    g_cnt[lane] = 0;
    g_cnt[lane + 32] = 0;
    if (lane == 0) {
        out[0] = (cnt > 0.f) ? tot / cnt : 0.f;
        g_done2 = 0;
    }
}

// ---------------------------------------------------------------------------
extern "C" void kernel_launch(void* const* d_in, const int* in_sizes, int n_in,
                              void* d_out, int out_size) {
    const float* x    = (const float*)d_in[0];
    const int*   mask = (const int*)d_in[1];
    // d_in[2..5] (W_ih, W_hh, b_ih, b_hh) and fc_b are dead: the LSTM head
    // contribution is constant along the logsumexp axis and cancels exactly.
    const float* fc_w = (const float*)d_in[6];
    float* out = (float*)d_out;

    fused_kernel<<<NBLK, 256>>>(x, fc_w, mask, out);
}